// round 15
// baseline (speedup 1.0000x reference)
#include <cuda_runtime.h>
#include <math.h>
#include <stdint.h>

#define NN 50000
#define NE 600000
#define FEATS 128
#define CAP 96   // slots per node; Poisson(12) => P(deg>96) ~ 1e-50

// -------------------- device scratch ---------------------------------------
__device__ __align__(128) int g_idx64;
__device__ __align__(128) int g_ocnt;
__device__ int g_cursor[NN];
__device__ __align__(16) int g_slots[NN * CAP];
__device__ int2 g_over[NE];                  // overflow — normally empty
__device__ float g_fx[(NN + 1) * FEATS];     // feat @ W^T ; row NN = zeros

// packed fp32x2 FMA (proven on this toolchain in R2-R5)
#define FFMA2(d, a, b) \
    asm("fma.rn.f32x2 %0, %1, %2, %0;" : "+l"(d) : "l"(a), "l"(b))

// ======================= init: cursors, sentinel slots, zero row, detect ====
__global__ void init_kernel(const void* __restrict__ src, int nNodes) {
    long i = (long)blockIdx.x * blockDim.x + threadIdx.x;
    // sentinel-fill slots (int4 stores): NN*CAP/4 int4s
    if (i < (long)NN * CAP / 4) {
        ((int4*)g_slots)[i] = make_int4(NN, NN, NN, NN);
    }
    if (i < NN) g_cursor[i] = 0;
    if (i < FEATS) g_fx[(long)NN * FEATS + i] = 0.f;   // zero row
    if (i == 0) {
        g_ocnt = 0;
        const long long* p = (const long long*)src;
        int is64 = 1;
        for (int k = 0; k < 64; k++) {
            long long v = p[k];
            if (v < 0 || v >= NN) { is64 = 0; break; }
        }
        g_idx64 = is64;
    }
}

// ======================= fill: slot bucketing (proven R14) ===================
__device__ __forceinline__ void fill_one(int d, int s) {
    int pos = atomicAdd(&g_cursor[d], 1);
    if (pos < CAP) {
        g_slots[d * CAP + pos] = s;
    } else {
        int o = atomicAdd(&g_ocnt, 1);
        g_over[o] = make_int2(d, s);
    }
}

__global__ void fill_kernel(const void* __restrict__ src,
                            const void* __restrict__ dst, int nE) {
    int i = (blockIdx.x * blockDim.x + threadIdx.x) * 2;
    if (g_idx64) {
        const long long* ps = (const long long*)src;
        const long long* pd = (const long long*)dst;
        if (i + 1 < nE) {
            longlong2 d2 = *(const longlong2*)(pd + i);
            longlong2 s2 = *(const longlong2*)(ps + i);
            fill_one((int)d2.x, (int)s2.x);
            fill_one((int)d2.y, (int)s2.y);
        } else if (i < nE) {
            fill_one((int)pd[i], (int)ps[i]);
        }
    } else {
        const int* ps = (const int*)src;
        const int* pd = (const int*)dst;
        if (i + 1 < nE) {
            int2 d2 = *(const int2*)(pd + i);
            int2 s2 = *(const int2*)(ps + i);
            fill_one(d2.x, s2.x);
            fill_one(d2.y, s2.y);
        } else if (i < nE) {
            fill_one(pd[i], ps[i]);
        }
    }
}

// ======================= GEMM via mma.sync bf16 split: fx = feat @ W^T ======
#define GSTR 136
#define SM_WH 0
#define SM_WL (SM_WH + 128 * GSTR * 2)
#define SM_AH (SM_WL + 128 * GSTR * 2)
#define SM_AL (SM_AH + 64 * GSTR * 2)
#define GEMM_SMEM (SM_AL + 64 * GSTR * 2)

#define MMA_BF16(c0, c1, c2, c3, a0, a1, a2, a3, b0, b1)                      \
    asm volatile(                                                             \
        "mma.sync.aligned.m16n8k16.row.col.f32.bf16.bf16.f32 "                \
        "{%0,%1,%2,%3}, {%4,%5,%6,%7}, {%8,%9}, {%0,%1,%2,%3};"               \
        : "+f"(c0), "+f"(c1), "+f"(c2), "+f"(c3)                              \
        : "r"(a0), "r"(a1), "r"(a2), "r"(a3), "r"(b0), "r"(b1))

__device__ __forceinline__ uint32_t pack_bf16(float lo, float hi) {
    uint32_t r;
    asm("cvt.rn.bf16x2.f32 %0, %1, %2;" : "=r"(r) : "f"(hi), "f"(lo));
    return r;
}

__device__ __forceinline__ void split4(float4 a, uint2& h, uint2& l) {
    uint32_t h01 = pack_bf16(a.x, a.y);
    uint32_t h23 = pack_bf16(a.z, a.w);
    float r0 = a.x - __uint_as_float(h01 << 16);
    float r1 = a.y - __uint_as_float(h01 & 0xffff0000u);
    float r2 = a.z - __uint_as_float(h23 << 16);
    float r3 = a.w - __uint_as_float(h23 & 0xffff0000u);
    h = make_uint2(h01, h23);
    l = make_uint2(pack_bf16(r0, r1), pack_bf16(r2, r3));
}

__global__ __launch_bounds__(256, 2) void gemm_mma_kernel(
    const float* __restrict__ feat, const float* __restrict__ W, int nNodes) {
    extern __shared__ char sm[];
    uint16_t* WH = (uint16_t*)(sm + SM_WH);
    uint16_t* WL = (uint16_t*)(sm + SM_WL);
    uint16_t* AH = (uint16_t*)(sm + SM_AH);
    uint16_t* AL = (uint16_t*)(sm + SM_AL);

    int tid = threadIdx.x;
    int lane = tid & 31;
    int warp = tid >> 5;
    int g = lane >> 2;
    int t = lane & 3;
    int mbase = (warp & 3) * 16;
    int nbase = (warp >> 2) * 64;

    for (int i = tid; i < 128 * 32; i += 256) {
        int j = i >> 5;
        int k4 = (i & 31) << 2;
        float4 w = __ldg((const float4*)(W + j * 128 + k4));
        uint2 h, l;
        split4(w, h, l);
        *(uint2*)(WH + j * GSTR + k4) = h;
        *(uint2*)(WL + j * GSTR + k4) = l;
    }

    for (int tile = blockIdx.x * 64; tile < nNodes; tile += gridDim.x * 64) {
        __syncthreads();

        for (int i = tid; i < 64 * 32; i += 256) {
            int r = i >> 5;
            int k4 = (i & 31) << 2;
            int row = tile + r;
            if (row >= nNodes) row = nNodes - 1;
            float4 a = __ldg((const float4*)(feat + (long)row * 128 + k4));
            uint2 h, l;
            split4(a, h, l);
            *(uint2*)(AH + r * GSTR + k4) = h;
            *(uint2*)(AL + r * GSTR + k4) = l;
        }
        __syncthreads();

        float c[8][4];
        #pragma unroll
        for (int nc = 0; nc < 8; nc++)
            #pragma unroll
            for (int i = 0; i < 4; i++) c[nc][i] = 0.f;

        #pragma unroll 1
        for (int kc = 0; kc < 8; kc++) {
            int k0 = kc * 16;
            const uint16_t* arh = AH + (mbase + g) * GSTR + k0;
            const uint16_t* arl = AL + (mbase + g) * GSTR + k0;
            uint32_t ah0 = *(const uint32_t*)(arh + t * 2);
            uint32_t ah1 = *(const uint32_t*)(arh + 8 * GSTR + t * 2);
            uint32_t ah2 = *(const uint32_t*)(arh + t * 2 + 8);
            uint32_t ah3 = *(const uint32_t*)(arh + 8 * GSTR + t * 2 + 8);
            uint32_t al0 = *(const uint32_t*)(arl + t * 2);
            uint32_t al1 = *(const uint32_t*)(arl + 8 * GSTR + t * 2);
            uint32_t al2 = *(const uint32_t*)(arl + t * 2 + 8);
            uint32_t al3 = *(const uint32_t*)(arl + 8 * GSTR + t * 2 + 8);

            #pragma unroll
            for (int nc = 0; nc < 8; nc++) {
                int j = nbase + nc * 8 + g;
                uint32_t bh0 = *(const uint32_t*)(WH + j * GSTR + k0 + t * 2);
                uint32_t bh1 = *(const uint32_t*)(WH + j * GSTR + k0 + t * 2 + 8);
                uint32_t bl0 = *(const uint32_t*)(WL + j * GSTR + k0 + t * 2);
                uint32_t bl1 = *(const uint32_t*)(WL + j * GSTR + k0 + t * 2 + 8);
                MMA_BF16(c[nc][0], c[nc][1], c[nc][2], c[nc][3],
                         ah0, ah1, ah2, ah3, bh0, bh1);
                MMA_BF16(c[nc][0], c[nc][1], c[nc][2], c[nc][3],
                         ah0, ah1, ah2, ah3, bl0, bl1);
                MMA_BF16(c[nc][0], c[nc][1], c[nc][2], c[nc][3],
                         al0, al1, al2, al3, bh0, bh1);
            }
        }

        int row0 = tile + mbase + g;
        int row1 = row0 + 8;
        #pragma unroll
        for (int nc = 0; nc < 8; nc++) {
            int n0 = nbase + nc * 8 + t * 2;
            if (row0 < nNodes)
                *(float2*)(g_fx + (long)row0 * 128 + n0) =
                    make_float2(c[nc][0], c[nc][1]);
            if (row1 < nNodes)
                *(float2*)(g_fx + (long)row1 * 128 + n0) =
                    make_float2(c[nc][2], c[nc][3]);
        }
    }
}

// ======================= gather + bias + tanh (sentinel-padded, FFMA2) ======
__global__ __launch_bounds__(256) void gather_tanh_kernel(
    const float* __restrict__ b, float* __restrict__ out, int nNodes) {
    int node = (blockIdx.x * 256 + threadIdx.x) >> 5;
    if (node >= nNodes) return;
    int l4 = (threadIdx.x & 31) * 4;
    float4 bv = *(const float4*)(b + l4);

    int cnt = __ldg(&g_cursor[node]);
    int ee = (cnt < CAP) ? cnt : CAP;
    int ee4 = (ee + 3) & ~3;                 // padded edges read sentinel -> +0
    const int4* slots4 = (const int4*)(g_slots + node * CAP);

    unsigned long long one2;
    asm("mov.b64 %0, {%1, %1};" : "=l"(one2) : "r"(0x3f800000u));  // {1.0f,1.0f}
    unsigned long long a0 = 0, a1 = 0;

    for (int e = 0; e < ee4; e += 4) {
        int4 ix = __ldg(&slots4[e >> 2]);
        #pragma unroll
        for (int u = 0; u < 4; u++) {
            int s = (u == 0) ? ix.x : (u == 1) ? ix.y : (u == 2) ? ix.z : ix.w;
            ulonglong2 v = *(const ulonglong2*)(g_fx + (long)s * FEATS + l4);
            FFMA2(a0, v.x, one2);
            FFMA2(a1, v.y, one2);
        }
    }

    float2 lo = *(float2*)&a0;
    float2 hi = *(float2*)&a1;
    float4 acc = make_float4(lo.x, lo.y, hi.x, hi.y);

    // overflow sweep (normally empty)
    if (cnt > CAP) {
        int ocnt = __ldg(&g_ocnt);
        for (int o = 0; o < ocnt; o++) {
            int2 pr = __ldg(&g_over[o]);
            if (pr.x == node) {
                float4 f = *(const float4*)(g_fx + (long)pr.y * FEATS + l4);
                acc.x += f.x; acc.y += f.y;
                acc.z += f.z; acc.w += f.w;
            }
        }
    }

    float4 o;
    o.x = tanhf(acc.x + bv.x);
    o.y = tanhf(acc.y + bv.y);
    o.z = tanhf(acc.z + bv.z);
    o.w = tanhf(acc.w + bv.w);
    *(float4*)(out + (long)node * FEATS + l4) = o;
}

// ---------------------------------------------------------------------------
extern "C" void kernel_launch(void* const* d_in, const int* in_sizes, int n_in,
                              void* d_out, int out_size) {
    const float* feature = (const float*)d_in[0];
    const float* W       = (const float*)d_in[1];
    const float* b       = (const float*)d_in[2];
    const void*  src     = d_in[3];
    const void*  dst     = d_in[4];
    float* out = (float*)d_out;

    int nEdges = in_sizes[3];
    int nNodes = out_size / FEATS;

    static cudaStream_t s2 = nullptr;
    static cudaEvent_t eFork = nullptr, eJoin = nullptr;
    if (!s2) {
        cudaStreamCreateWithFlags(&s2, cudaStreamNonBlocking);
        cudaEventCreateWithFlags(&eFork, cudaEventDisableTiming);
        cudaEventCreateWithFlags(&eJoin, cudaEventDisableTiming);
        cudaFuncSetAttribute(gemm_mma_kernel,
                             cudaFuncAttributeMaxDynamicSharedMemorySize, GEMM_SMEM);
    }

    // fork: mma GEMM (feat @ W^T) on s2 overlaps init+fill on stream 0
    cudaEventRecord(eFork, 0);
    cudaStreamWaitEvent(s2, eFork, 0);
    gemm_mma_kernel<<<296, 256, GEMM_SMEM, s2>>>(feature, W, nNodes);
    cudaEventRecord(eJoin, s2);

    long initN = (long)NN * CAP / 4;   // sentinel int4 stores dominate
    init_kernel<<<(int)((initN + 511) / 512), 512>>>(src, nNodes);
    fill_kernel<<<(nEdges / 2 + 511) / 512, 512>>>(src, dst, nEdges);

    // join, then gather + bias + tanh
    cudaStreamWaitEvent(0, eJoin, 0);
    gather_tanh_kernel<<<(nNodes * 32 + 255) / 256, 256>>>(b, out, nNodes);
}

// round 16
// speedup vs baseline: 1.1042x; 1.1042x over previous
#include <cuda_runtime.h>
#include <cuda_fp16.h>
#include <math.h>
#include <stdint.h>

#define NN 50000
#define NE 600000
#define FEATS 128
#define CAP 96   // slots per node; Poisson(12) => P(deg>96) ~ 1e-50

// -------------------- device scratch ---------------------------------------
__device__ __align__(128) int g_idx64;
__device__ __align__(128) int g_ocnt;
__device__ int g_cursor[NN];
__device__ __align__(16) int g_slots[NN * CAP];   // zero-init; always in-range
__device__ int2 g_over[NE];                       // overflow — normally empty
__device__ __half g_fxh[NN * FEATS];              // feat @ W^T, fp16

// ======================= init: cursors + overflow cnt + detect ==============
__global__ void init_kernel(const void* __restrict__ src) {
    int i = blockIdx.x * blockDim.x + threadIdx.x;
    if (i < NN) g_cursor[i] = 0;
    if (i == 0) {
        g_ocnt = 0;
        const long long* p = (const long long*)src;
        int is64 = 1;
        for (int k = 0; k < 64; k++) {
            long long v = p[k];
            if (v < 0 || v >= NN) { is64 = 0; break; }
        }
        g_idx64 = is64;
    }
}

// ======================= fill: slot bucketing (proven R14/R15) ===============
__device__ __forceinline__ void fill_one(int d, int s) {
    int pos = atomicAdd(&g_cursor[d], 1);
    if (pos < CAP) {
        g_slots[d * CAP + pos] = s;
    } else {
        int o = atomicAdd(&g_ocnt, 1);
        g_over[o] = make_int2(d, s);
    }
}

__global__ void fill_kernel(const void* __restrict__ src,
                            const void* __restrict__ dst, int nE) {
    int i = (blockIdx.x * blockDim.x + threadIdx.x) * 2;
    if (g_idx64) {
        const long long* ps = (const long long*)src;
        const long long* pd = (const long long*)dst;
        if (i + 1 < nE) {
            longlong2 d2 = *(const longlong2*)(pd + i);
            longlong2 s2 = *(const longlong2*)(ps + i);
            fill_one((int)d2.x, (int)s2.x);
            fill_one((int)d2.y, (int)s2.y);
        } else if (i < nE) {
            fill_one((int)pd[i], (int)ps[i]);
        }
    } else {
        const int* ps = (const int*)src;
        const int* pd = (const int*)dst;
        if (i + 1 < nE) {
            int2 d2 = *(const int2*)(pd + i);
            int2 s2 = *(const int2*)(ps + i);
            fill_one(d2.x, s2.x);
            fill_one(d2.y, s2.y);
        } else if (i < nE) {
            fill_one(pd[i], ps[i]);
        }
    }
}

// ======================= GEMM via mma.sync bf16 split: fxh = feat @ W^T =====
#define GSTR 136
#define SM_WH 0
#define SM_WL (SM_WH + 128 * GSTR * 2)
#define SM_AH (SM_WL + 128 * GSTR * 2)
#define SM_AL (SM_AH + 64 * GSTR * 2)
#define GEMM_SMEM (SM_AL + 64 * GSTR * 2)

#define MMA_BF16(c0, c1, c2, c3, a0, a1, a2, a3, b0, b1)                      \
    asm volatile(                                                             \
        "mma.sync.aligned.m16n8k16.row.col.f32.bf16.bf16.f32 "                \
        "{%0,%1,%2,%3}, {%4,%5,%6,%7}, {%8,%9}, {%0,%1,%2,%3};"               \
        : "+f"(c0), "+f"(c1), "+f"(c2), "+f"(c3)                              \
        : "r"(a0), "r"(a1), "r"(a2), "r"(a3), "r"(b0), "r"(b1))

__device__ __forceinline__ uint32_t pack_bf16(float lo, float hi) {
    uint32_t r;
    asm("cvt.rn.bf16x2.f32 %0, %1, %2;" : "=r"(r) : "f"(hi), "f"(lo));
    return r;
}

__device__ __forceinline__ void split4(float4 a, uint2& h, uint2& l) {
    uint32_t h01 = pack_bf16(a.x, a.y);
    uint32_t h23 = pack_bf16(a.z, a.w);
    float r0 = a.x - __uint_as_float(h01 << 16);
    float r1 = a.y - __uint_as_float(h01 & 0xffff0000u);
    float r2 = a.z - __uint_as_float(h23 << 16);
    float r3 = a.w - __uint_as_float(h23 & 0xffff0000u);
    h = make_uint2(h01, h23);
    l = make_uint2(pack_bf16(r0, r1), pack_bf16(r2, r3));
}

__global__ __launch_bounds__(256, 2) void gemm_mma_kernel(
    const float* __restrict__ feat, const float* __restrict__ W, int nNodes) {
    extern __shared__ char sm[];
    uint16_t* WH = (uint16_t*)(sm + SM_WH);
    uint16_t* WL = (uint16_t*)(sm + SM_WL);
    uint16_t* AH = (uint16_t*)(sm + SM_AH);
    uint16_t* AL = (uint16_t*)(sm + SM_AL);

    int tid = threadIdx.x;
    int lane = tid & 31;
    int warp = tid >> 5;
    int g = lane >> 2;
    int t = lane & 3;
    int mbase = (warp & 3) * 16;
    int nbase = (warp >> 2) * 64;

    for (int i = tid; i < 128 * 32; i += 256) {
        int j = i >> 5;
        int k4 = (i & 31) << 2;
        float4 w = __ldg((const float4*)(W + j * 128 + k4));
        uint2 h, l;
        split4(w, h, l);
        *(uint2*)(WH + j * GSTR + k4) = h;
        *(uint2*)(WL + j * GSTR + k4) = l;
    }

    for (int tile = blockIdx.x * 64; tile < nNodes; tile += gridDim.x * 64) {
        __syncthreads();

        for (int i = tid; i < 64 * 32; i += 256) {
            int r = i >> 5;
            int k4 = (i & 31) << 2;
            int row = tile + r;
            if (row >= nNodes) row = nNodes - 1;
            float4 a = __ldg((const float4*)(feat + (long)row * 128 + k4));
            uint2 h, l;
            split4(a, h, l);
            *(uint2*)(AH + r * GSTR + k4) = h;
            *(uint2*)(AL + r * GSTR + k4) = l;
        }
        __syncthreads();

        float c[8][4];
        #pragma unroll
        for (int nc = 0; nc < 8; nc++)
            #pragma unroll
            for (int i = 0; i < 4; i++) c[nc][i] = 0.f;

        #pragma unroll 1
        for (int kc = 0; kc < 8; kc++) {
            int k0 = kc * 16;
            const uint16_t* arh = AH + (mbase + g) * GSTR + k0;
            const uint16_t* arl = AL + (mbase + g) * GSTR + k0;
            uint32_t ah0 = *(const uint32_t*)(arh + t * 2);
            uint32_t ah1 = *(const uint32_t*)(arh + 8 * GSTR + t * 2);
            uint32_t ah2 = *(const uint32_t*)(arh + t * 2 + 8);
            uint32_t ah3 = *(const uint32_t*)(arh + 8 * GSTR + t * 2 + 8);
            uint32_t al0 = *(const uint32_t*)(arl + t * 2);
            uint32_t al1 = *(const uint32_t*)(arl + 8 * GSTR + t * 2);
            uint32_t al2 = *(const uint32_t*)(arl + t * 2 + 8);
            uint32_t al3 = *(const uint32_t*)(arl + 8 * GSTR + t * 2 + 8);

            #pragma unroll
            for (int nc = 0; nc < 8; nc++) {
                int j = nbase + nc * 8 + g;
                uint32_t bh0 = *(const uint32_t*)(WH + j * GSTR + k0 + t * 2);
                uint32_t bh1 = *(const uint32_t*)(WH + j * GSTR + k0 + t * 2 + 8);
                uint32_t bl0 = *(const uint32_t*)(WL + j * GSTR + k0 + t * 2);
                uint32_t bl1 = *(const uint32_t*)(WL + j * GSTR + k0 + t * 2 + 8);
                MMA_BF16(c[nc][0], c[nc][1], c[nc][2], c[nc][3],
                         ah0, ah1, ah2, ah3, bh0, bh1);
                MMA_BF16(c[nc][0], c[nc][1], c[nc][2], c[nc][3],
                         ah0, ah1, ah2, ah3, bl0, bl1);
                MMA_BF16(c[nc][0], c[nc][1], c[nc][2], c[nc][3],
                         al0, al1, al2, al3, bh0, bh1);
            }
        }

        // epilogue: pack fp16, store half2 per (row, col-pair)
        int row0 = tile + mbase + g;
        int row1 = row0 + 8;
        #pragma unroll
        for (int nc = 0; nc < 8; nc++) {
            int n0 = nbase + nc * 8 + t * 2;
            if (row0 < nNodes) {
                half2 h = __float22half2_rn(make_float2(c[nc][0], c[nc][1]));
                *(half2*)(g_fxh + (long)row0 * 128 + n0) = h;
            }
            if (row1 < nNodes) {
                half2 h = __float22half2_rn(make_float2(c[nc][2], c[nc][3]));
                *(half2*)(g_fxh + (long)row1 * 128 + n0) = h;
            }
        }
    }
}

// ======================= gather + bias + tanh (fp16 reads, fp32 accum) ======
__global__ __launch_bounds__(256) void gather_tanh_kernel(
    const float* __restrict__ b, float* __restrict__ out, int nNodes) {
    int node = (blockIdx.x * 256 + threadIdx.x) >> 5;
    if (node >= nNodes) return;
    int l4 = (threadIdx.x & 31) * 4;
    float4 bv = *(const float4*)(b + l4);

    int cnt = __ldg(&g_cursor[node]);
    int ee = (cnt < CAP) ? cnt : CAP;
    int full = ee & ~3;
    const int4* slots4 = (const int4*)(g_slots + node * CAP);

    float4 acc = make_float4(0.f, 0.f, 0.f, 0.f);

    // main loop: full int4 groups, unpredicated
    for (int e = 0; e < full; e += 4) {
        int4 ix = __ldg(&slots4[e >> 2]);
        #pragma unroll
        for (int u = 0; u < 4; u++) {
            int s = (u == 0) ? ix.x : (u == 1) ? ix.y : (u == 2) ? ix.z : ix.w;
            uint2 v = *(const uint2*)(g_fxh + (long)s * FEATS + l4);
            float2 f0 = __half22float2(*(half2*)&v.x);
            float2 f1 = __half22float2(*(half2*)&v.y);
            acc.x += f0.x; acc.y += f0.y;
            acc.z += f1.x; acc.w += f1.y;
        }
    }
    // tail group: <=3 predicated adds (stale slot contents are in-range)
    if (full < ee) {
        int4 ix = __ldg(&slots4[full >> 2]);
        #pragma unroll
        for (int u = 0; u < 4; u++) {
            int j = full + u;
            int s = (u == 0) ? ix.x : (u == 1) ? ix.y : (u == 2) ? ix.z : ix.w;
            uint2 v = *(const uint2*)(g_fxh + (long)s * FEATS + l4);
            float2 f0 = __half22float2(*(half2*)&v.x);
            float2 f1 = __half22float2(*(half2*)&v.y);
            if (j < ee) {
                acc.x += f0.x; acc.y += f0.y;
                acc.z += f1.x; acc.w += f1.y;
            }
        }
    }

    // overflow sweep (normally empty)
    if (cnt > CAP) {
        int ocnt = __ldg(&g_ocnt);
        for (int o = 0; o < ocnt; o++) {
            int2 pr = __ldg(&g_over[o]);
            if (pr.x == node) {
                uint2 v = *(const uint2*)(g_fxh + (long)pr.y * FEATS + l4);
                float2 f0 = __half22float2(*(half2*)&v.x);
                float2 f1 = __half22float2(*(half2*)&v.y);
                acc.x += f0.x; acc.y += f0.y;
                acc.z += f1.x; acc.w += f1.y;
            }
        }
    }

    float4 o;
    o.x = tanhf(acc.x + bv.x);
    o.y = tanhf(acc.y + bv.y);
    o.z = tanhf(acc.z + bv.z);
    o.w = tanhf(acc.w + bv.w);
    *(float4*)(out + (long)node * FEATS + l4) = o;
}

// ---------------------------------------------------------------------------
extern "C" void kernel_launch(void* const* d_in, const int* in_sizes, int n_in,
                              void* d_out, int out_size) {
    const float* feature = (const float*)d_in[0];
    const float* W       = (const float*)d_in[1];
    const float* b       = (const float*)d_in[2];
    const void*  src     = d_in[3];
    const void*  dst     = d_in[4];
    float* out = (float*)d_out;

    int nEdges = in_sizes[3];
    int nNodes = out_size / FEATS;

    static cudaStream_t s2 = nullptr;
    static cudaEvent_t eFork = nullptr, eJoin = nullptr;
    if (!s2) {
        cudaStreamCreateWithFlags(&s2, cudaStreamNonBlocking);
        cudaEventCreateWithFlags(&eFork, cudaEventDisableTiming);
        cudaEventCreateWithFlags(&eJoin, cudaEventDisableTiming);
        cudaFuncSetAttribute(gemm_mma_kernel,
                             cudaFuncAttributeMaxDynamicSharedMemorySize, GEMM_SMEM);
    }

    // fork: mma GEMM (feat @ W^T -> fp16) on s2 overlaps init+fill on stream 0
    cudaEventRecord(eFork, 0);
    cudaStreamWaitEvent(s2, eFork, 0);
    gemm_mma_kernel<<<296, 256, GEMM_SMEM, s2>>>(feature, W, nNodes);
    cudaEventRecord(eJoin, s2);

    init_kernel<<<(NN + 1023) / 1024, 1024>>>(src);
    fill_kernel<<<(nEdges / 2 + 511) / 512, 512>>>(src, dst, nEdges);

    // join, then gather + bias + tanh
    cudaStreamWaitEvent(0, eJoin, 0);
    gather_tanh_kernel<<<(nNodes * 32 + 255) / 256, 256>>>(b, out, nNodes);
}

// round 17
// speedup vs baseline: 1.1108x; 1.0059x over previous
#include <cuda_runtime.h>
#include <cuda_fp16.h>
#include <math.h>
#include <stdint.h>

#define NN 50000
#define NE 600000
#define FEATS 128
#define CAP 96   // slots per node; Poisson(12) => P(deg>96) ~ 1e-50

// -------------------- device scratch ---------------------------------------
__device__ __align__(128) int g_idx64;
__device__ __align__(128) int g_ocnt;
__device__ int g_cursor[NN];
__device__ __align__(16) int g_slots[NN * CAP];   // zero-init; always in-range
__device__ int2 g_over[NE];                       // overflow — normally empty
__device__ __align__(16) __half g_fxh[(NN + 1) * FEATS];  // fp16 fx; row NN = 0

// ======================= init: cursors + sentinel row + detect ==============
__global__ void init_kernel(const void* __restrict__ src) {
    int i = blockIdx.x * blockDim.x + threadIdx.x;
    if (i < NN) g_cursor[i] = 0;
    if (i < FEATS / 8)
        ((uint4*)(g_fxh + (long)NN * FEATS))[i] = make_uint4(0, 0, 0, 0);
    if (i == 0) {
        g_ocnt = 0;
        const long long* p = (const long long*)src;
        int is64 = 1;
        for (int k = 0; k < 64; k++) {
            long long v = p[k];
            if (v < 0 || v >= NN) { is64 = 0; break; }
        }
        g_idx64 = is64;
    }
}

// ======================= fill: slot bucketing (proven R14-R16) ===============
__device__ __forceinline__ void fill_one(int d, int s) {
    int pos = atomicAdd(&g_cursor[d], 1);
    if (pos < CAP) {
        g_slots[d * CAP + pos] = s;
    } else {
        int o = atomicAdd(&g_ocnt, 1);
        g_over[o] = make_int2(d, s);
    }
}

__global__ void fill_kernel(const void* __restrict__ src,
                            const void* __restrict__ dst, int nE) {
    int i = (blockIdx.x * blockDim.x + threadIdx.x) * 2;
    if (g_idx64) {
        const long long* ps = (const long long*)src;
        const long long* pd = (const long long*)dst;
        if (i + 1 < nE) {
            longlong2 d2 = *(const longlong2*)(pd + i);
            longlong2 s2 = *(const longlong2*)(ps + i);
            fill_one((int)d2.x, (int)s2.x);
            fill_one((int)d2.y, (int)s2.y);
        } else if (i < nE) {
            fill_one((int)pd[i], (int)ps[i]);
        }
    } else {
        const int* ps = (const int*)src;
        const int* pd = (const int*)dst;
        if (i + 1 < nE) {
            int2 d2 = *(const int2*)(pd + i);
            int2 s2 = *(const int2*)(ps + i);
            fill_one(d2.x, s2.x);
            fill_one(d2.y, s2.y);
        } else if (i < nE) {
            fill_one(pd[i], ps[i]);
        }
    }
}

// ======================= GEMM via mma.sync bf16 split: fxh = feat @ W^T =====
#define GSTR 136
#define SM_WH 0
#define SM_WL (SM_WH + 128 * GSTR * 2)
#define SM_AH (SM_WL + 128 * GSTR * 2)
#define SM_AL (SM_AH + 64 * GSTR * 2)
#define GEMM_SMEM (SM_AL + 64 * GSTR * 2)

#define MMA_BF16(c0, c1, c2, c3, a0, a1, a2, a3, b0, b1)                      \
    asm volatile(                                                             \
        "mma.sync.aligned.m16n8k16.row.col.f32.bf16.bf16.f32 "                \
        "{%0,%1,%2,%3}, {%4,%5,%6,%7}, {%8,%9}, {%0,%1,%2,%3};"               \
        : "+f"(c0), "+f"(c1), "+f"(c2), "+f"(c3)                              \
        : "r"(a0), "r"(a1), "r"(a2), "r"(a3), "r"(b0), "r"(b1))

__device__ __forceinline__ uint32_t pack_bf16(float lo, float hi) {
    uint32_t r;
    asm("cvt.rn.bf16x2.f32 %0, %1, %2;" : "=r"(r) : "f"(hi), "f"(lo));
    return r;
}

__device__ __forceinline__ void split4(float4 a, uint2& h, uint2& l) {
    uint32_t h01 = pack_bf16(a.x, a.y);
    uint32_t h23 = pack_bf16(a.z, a.w);
    float r0 = a.x - __uint_as_float(h01 << 16);
    float r1 = a.y - __uint_as_float(h01 & 0xffff0000u);
    float r2 = a.z - __uint_as_float(h23 << 16);
    float r3 = a.w - __uint_as_float(h23 & 0xffff0000u);
    h = make_uint2(h01, h23);
    l = make_uint2(pack_bf16(r0, r1), pack_bf16(r2, r3));
}

__global__ __launch_bounds__(256, 2) void gemm_mma_kernel(
    const float* __restrict__ feat, const float* __restrict__ W, int nNodes) {
    extern __shared__ char sm[];
    uint16_t* WH = (uint16_t*)(sm + SM_WH);
    uint16_t* WL = (uint16_t*)(sm + SM_WL);
    uint16_t* AH = (uint16_t*)(sm + SM_AH);
    uint16_t* AL = (uint16_t*)(sm + SM_AL);

    int tid = threadIdx.x;
    int lane = tid & 31;
    int warp = tid >> 5;
    int g = lane >> 2;
    int t = lane & 3;
    int mbase = (warp & 3) * 16;
    int nbase = (warp >> 2) * 64;

    for (int i = tid; i < 128 * 32; i += 256) {
        int j = i >> 5;
        int k4 = (i & 31) << 2;
        float4 w = __ldg((const float4*)(W + j * 128 + k4));
        uint2 h, l;
        split4(w, h, l);
        *(uint2*)(WH + j * GSTR + k4) = h;
        *(uint2*)(WL + j * GSTR + k4) = l;
    }

    for (int tile = blockIdx.x * 64; tile < nNodes; tile += gridDim.x * 64) {
        __syncthreads();

        for (int i = tid; i < 64 * 32; i += 256) {
            int r = i >> 5;
            int k4 = (i & 31) << 2;
            int row = tile + r;
            if (row >= nNodes) row = nNodes - 1;
            float4 a = __ldg((const float4*)(feat + (long)row * 128 + k4));
            uint2 h, l;
            split4(a, h, l);
            *(uint2*)(AH + r * GSTR + k4) = h;
            *(uint2*)(AL + r * GSTR + k4) = l;
        }
        __syncthreads();

        float c[8][4];
        #pragma unroll
        for (int nc = 0; nc < 8; nc++)
            #pragma unroll
            for (int i = 0; i < 4; i++) c[nc][i] = 0.f;

        #pragma unroll 1
        for (int kc = 0; kc < 8; kc++) {
            int k0 = kc * 16;
            const uint16_t* arh = AH + (mbase + g) * GSTR + k0;
            const uint16_t* arl = AL + (mbase + g) * GSTR + k0;
            uint32_t ah0 = *(const uint32_t*)(arh + t * 2);
            uint32_t ah1 = *(const uint32_t*)(arh + 8 * GSTR + t * 2);
            uint32_t ah2 = *(const uint32_t*)(arh + t * 2 + 8);
            uint32_t ah3 = *(const uint32_t*)(arh + 8 * GSTR + t * 2 + 8);
            uint32_t al0 = *(const uint32_t*)(arl + t * 2);
            uint32_t al1 = *(const uint32_t*)(arl + 8 * GSTR + t * 2);
            uint32_t al2 = *(const uint32_t*)(arl + t * 2 + 8);
            uint32_t al3 = *(const uint32_t*)(arl + 8 * GSTR + t * 2 + 8);

            #pragma unroll
            for (int nc = 0; nc < 8; nc++) {
                int j = nbase + nc * 8 + g;
                uint32_t bh0 = *(const uint32_t*)(WH + j * GSTR + k0 + t * 2);
                uint32_t bh1 = *(const uint32_t*)(WH + j * GSTR + k0 + t * 2 + 8);
                uint32_t bl0 = *(const uint32_t*)(WL + j * GSTR + k0 + t * 2);
                uint32_t bl1 = *(const uint32_t*)(WL + j * GSTR + k0 + t * 2 + 8);
                MMA_BF16(c[nc][0], c[nc][1], c[nc][2], c[nc][3],
                         ah0, ah1, ah2, ah3, bh0, bh1);
                MMA_BF16(c[nc][0], c[nc][1], c[nc][2], c[nc][3],
                         ah0, ah1, ah2, ah3, bl0, bl1);
                MMA_BF16(c[nc][0], c[nc][1], c[nc][2], c[nc][3],
                         al0, al1, al2, al3, bh0, bh1);
            }
        }

        int row0 = tile + mbase + g;
        int row1 = row0 + 8;
        #pragma unroll
        for (int nc = 0; nc < 8; nc++) {
            int n0 = nbase + nc * 8 + t * 2;
            if (row0 < nNodes) {
                half2 h = __float22half2_rn(make_float2(c[nc][0], c[nc][1]));
                *(half2*)(g_fxh + (long)row0 * 128 + n0) = h;
            }
            if (row1 < nNodes) {
                half2 h = __float22half2_rn(make_float2(c[nc][2], c[nc][3]));
                *(half2*)(g_fxh + (long)row1 * 128 + n0) = h;
            }
        }
    }
}

// ======================= gather + bias + tanh: 2 nodes per warp =============
// Lanes 0-15 = node A, lanes 16-31 = node B; each lane covers 8 fp16 feats
// (one LDG.128 per edge-step serves both nodes). Exhausted lanes read the
// zero sentinel row (index NN) via a SEL clamp — no predication, no tail.
__global__ __launch_bounds__(256) void gather_tanh_kernel(
    const float* __restrict__ b, float* __restrict__ out, int nNodes) {
    int gw = (blockIdx.x * 256 + threadIdx.x) >> 5;
    int lane = threadIdx.x & 31;
    int node = gw * 2 + (lane >> 4);
    if (node >= nNodes) node = nNodes - 1;   // dup warps rewrite same row: benign
    int f8 = (lane & 15) * 8;

    float4 bv0 = *(const float4*)(b + f8);
    float4 bv1 = *(const float4*)(b + f8 + 4);

    int cnt = __ldg(&g_cursor[node]);
    int ee = (cnt < CAP) ? cnt : CAP;
    int eo = __shfl_xor_sync(0xffffffffu, ee, 16);
    int eemax = (ee > eo) ? ee : eo;
    const int4* slots4 = (const int4*)(g_slots + node * CAP);

    float a0 = 0.f, a1 = 0.f, a2 = 0.f, a3 = 0.f;
    float a4 = 0.f, a5 = 0.f, a6 = 0.f, a7 = 0.f;

    for (int e = 0; e < eemax; e += 4) {
        int4 ix = __ldg(&slots4[e >> 2]);
        #pragma unroll
        for (int u = 0; u < 4; u++) {
            int j = e + u;
            int s = (u == 0) ? ix.x : (u == 1) ? ix.y : (u == 2) ? ix.z : ix.w;
            s = (j < ee) ? s : NN;   // sentinel zero row
            uint4 v = *(const uint4*)(g_fxh + (long)s * FEATS + f8);
            float2 f0 = __half22float2(*(half2*)&v.x);
            float2 f1 = __half22float2(*(half2*)&v.y);
            float2 f2 = __half22float2(*(half2*)&v.z);
            float2 f3 = __half22float2(*(half2*)&v.w);
            a0 += f0.x; a1 += f0.y; a2 += f1.x; a3 += f1.y;
            a4 += f2.x; a5 += f2.y; a6 += f3.x; a7 += f3.y;
        }
    }

    // overflow sweep (normally empty)
    if (cnt > CAP) {
        int ocnt = __ldg(&g_ocnt);
        for (int o = 0; o < ocnt; o++) {
            int2 pr = __ldg(&g_over[o]);
            if (pr.x == node) {
                uint4 v = *(const uint4*)(g_fxh + (long)pr.y * FEATS + f8);
                float2 f0 = __half22float2(*(half2*)&v.x);
                float2 f1 = __half22float2(*(half2*)&v.y);
                float2 f2 = __half22float2(*(half2*)&v.z);
                float2 f3 = __half22float2(*(half2*)&v.w);
                a0 += f0.x; a1 += f0.y; a2 += f1.x; a3 += f1.y;
                a4 += f2.x; a5 += f2.y; a6 += f3.x; a7 += f3.y;
            }
        }
    }

    float4 o0, o1;
    o0.x = tanhf(a0 + bv0.x);
    o0.y = tanhf(a1 + bv0.y);
    o0.z = tanhf(a2 + bv0.z);
    o0.w = tanhf(a3 + bv0.w);
    o1.x = tanhf(a4 + bv1.x);
    o1.y = tanhf(a5 + bv1.y);
    o1.z = tanhf(a6 + bv1.z);
    o1.w = tanhf(a7 + bv1.w);
    *(float4*)(out + (long)node * FEATS + f8) = o0;
    *(float4*)(out + (long)node * FEATS + f8 + 4) = o1;
}

// ---------------------------------------------------------------------------
extern "C" void kernel_launch(void* const* d_in, const int* in_sizes, int n_in,
                              void* d_out, int out_size) {
    const float* feature = (const float*)d_in[0];
    const float* W       = (const float*)d_in[1];
    const float* b       = (const float*)d_in[2];
    const void*  src     = d_in[3];
    const void*  dst     = d_in[4];
    float* out = (float*)d_out;

    int nEdges = in_sizes[3];
    int nNodes = out_size / FEATS;

    static cudaStream_t s2 = nullptr;
    static cudaEvent_t eFork = nullptr, eJoin = nullptr;
    if (!s2) {
        cudaStreamCreateWithFlags(&s2, cudaStreamNonBlocking);
        cudaEventCreateWithFlags(&eFork, cudaEventDisableTiming);
        cudaEventCreateWithFlags(&eJoin, cudaEventDisableTiming);
        cudaFuncSetAttribute(gemm_mma_kernel,
                             cudaFuncAttributeMaxDynamicSharedMemorySize, GEMM_SMEM);
    }

    // fork: mma GEMM (feat @ W^T -> fp16) on s2 overlaps init+fill on stream 0
    cudaEventRecord(eFork, 0);
    cudaStreamWaitEvent(s2, eFork, 0);
    gemm_mma_kernel<<<296, 256, GEMM_SMEM, s2>>>(feature, W, nNodes);
    cudaEventRecord(eJoin, s2);

    init_kernel<<<(NN + 1023) / 1024, 1024>>>(src);
    fill_kernel<<<(nEdges / 2 + 511) / 512, 512>>>(src, dst, nEdges);

    // join, then gather + bias + tanh (2 nodes per warp)
    cudaStreamWaitEvent(0, eJoin, 0);
    int warps = (nNodes + 1) / 2;
    gather_tanh_kernel<<<(warps * 32 + 255) / 256, 256>>>(b, out, nNodes);
}